// round 16
// baseline (speedup 1.0000x reference)
#include <cuda_runtime.h>
#include <cuda_fp16.h>
#include <stdint.h>
#include <math.h>

#define IMG   320
#define NPIX  1024
#define YROWB 144           // 72 halfs; stride%128=16 -> conflict-free ldmatrix

// shared layout (bytes): red overlays timg (timg dead after build)
#define SM_TIMG 0           // 12288 B (red: float4[512]=8KB after main loop)
#define SM_SQS  12288       // float[1024]: sq * log2e^2
#define SM_AUXT 16384       // half[4][1032]: V^T rows {I0, I1, I2, 1}
#define AUXT_STRIDE 1032
#define SM_Y    24704       // half[1024][72] (base%128==0 keeps bank layout)
#define SMEM_TOTAL (SM_Y + NPIX * YROWB)   // 172160

#define LOG2E2  2.0813689810056077f     // (log2 e)^2
#define NEG2L2 (-4.1627379620112153f)   // -2*(log2 e)^2

typedef unsigned long long ull;

__device__ __forceinline__ uint32_t smem_u32(const void* p) {
    uint32_t a;
    asm("{ .reg .u64 t; cvta.to.shared.u64 t, %1; cvt.u32.u64 %0, t; }" : "=r"(a) : "l"(p));
    return a;
}
__device__ __forceinline__ ull fma2(ull a, ull b, ull c) {
    ull d; asm("fma.rn.f32x2 %0, %1, %2, %3;" : "=l"(d) : "l"(a), "l"(b), "l"(c));
    return d;
}
__device__ __forceinline__ ull add2(ull a, ull b) {
    ull d; asm("add.rn.f32x2 %0, %1, %2;" : "=l"(d) : "l"(a), "l"(b));
    return d;
}
__device__ __forceinline__ ull pack2(float lo, float hi) {
    ull d; asm("mov.b64 %0, {%1, %2};" : "=l"(d) : "f"(lo), "f"(hi));
    return d;
}
__device__ __forceinline__ float2 unpack2(ull v) {
    float lo, hi; asm("mov.b64 {%0, %1}, %2;" : "=f"(lo), "=f"(hi) : "l"(v));
    return make_float2(lo, hi);
}
__device__ __forceinline__ float sqrta(float x) {
    float y; asm("sqrt.approx.f32 %0, %1;" : "=f"(y) : "f"(x)); return y;
}
__device__ __forceinline__ uint32_t cvt_h2(float hi, float lo) {   // h1=hi, h0=lo
    uint32_t r; asm("cvt.rn.f16x2.f32 %0, %1, %2;" : "=r"(r) : "f"(hi), "f"(lo));
    return r;
}
__device__ __forceinline__ uint32_t ex2h2(uint32_t a) {            // MUFU, 2 results
    uint32_t r; asm("ex2.approx.f16x2 %0, %1;" : "=r"(r) : "r"(a));
    return r;
}

#define LDSM4(r, addr) \
    asm volatile("ldmatrix.sync.aligned.m8n8.x4.shared.b16 {%0,%1,%2,%3}, [%4];" \
        : "=r"((r)[0]), "=r"((r)[1]), "=r"((r)[2]), "=r"((r)[3]) : "r"(addr))
#define LDSM2(r, addr) \
    asm volatile("ldmatrix.sync.aligned.m8n8.x2.shared.b16 {%0,%1}, [%2];" \
        : "=r"((r)[0]), "=r"((r)[1]) : "r"(addr))
#define MMA16816(c, a, b0, b1) \
    asm volatile("mma.sync.aligned.m16n8k16.row.col.f32.f16.f16.f32 " \
        "{%0,%1,%2,%3}, {%4,%5,%6,%7}, {%8,%9}, {%0,%1,%2,%3};" \
        : "+f"((c)[0]), "+f"((c)[1]), "+f"((c)[2]), "+f"((c)[3]) \
        : "r"((a)[0]), "r"((a)[1]), "r"((a)[2]), "r"((a)[3]), "r"(b0), "r"(b1))
#define MMA16808(c, a, b0) \
    asm volatile("mma.sync.aligned.m16n8k8.row.col.f32.f16.f16.f32 " \
        "{%0,%1,%2,%3}, {%4,%5}, {%6}, {%0,%1,%2,%3};" \
        : "+f"((c)[0]), "+f"((c)[1]), "+f"((c)[2]), "+f"((c)[3]) \
        : "r"((a)[0]), "r"((a)[1]), "r"(b0))

__global__ __launch_bounds__(512, 1)
void nlm_hmma_kernel(const float* __restrict__ img, float* __restrict__ out)
{
    extern __shared__ char sm[];
    float*   timg = (float*)(sm + SM_TIMG);
    float4*  red  = (float4*)(sm + SM_TIMG);      // overlays timg after main loop
    float*   sqs  = (float*)(sm + SM_SQS);
    __half*  auxT = (__half*)(sm + SM_AUXT);
    char*    Yb   = sm + SM_Y;

    const int bid  = blockIdx.x;
    const int tile = bid >> 2, nb = bid & 3;      // 256 rows per CTA
    const int ti = tile / 10, tj = tile % 10;
    const int tid = threadIdx.x;
    const int gb = ti * 32 * IMG + tj * 32;

    // ---- tile image -> smem ----
    for (int i = tid; i < 3 * NPIX; i += 512) {
        int ch = i >> 10, pix = i & 1023;
        timg[i] = img[ch * (IMG * IMG) + gb + (pix >> 5) * IMG + (pix & 31)];
    }
    __syncthreads();

    // ---- build fp16 features Y[1024][72] + V^T (fp16) + scaled norms ----
    for (int p = tid; p < NPIX; p += 512) {
        int r = p >> 5, c = p & 31;
        __half hl[72];
        float sq = 0.f;
        #pragma unroll
        for (int k = 0; k < 25; k++) {
            if (k == 12) continue;
            int kk = (k < 12) ? k : k - 1;
            int rr = min(max(r + k / 5 - 2, 0), 31);
            int cc = min(max(c + k % 5 - 2, 0), 31);
            int off = rr * 32 + cc;
            #pragma unroll
            for (int ch = 0; ch < 3; ch++) {
                float x = timg[ch * NPIX + off];
                __half h = __float2half_rn(x);
                float xr = __half2float(h);
                sq = fmaf(xr, xr, sq);
                hl[ch * 24 + kk] = h;
            }
        }
        __half2* yrow = (__half2*)(Yb + p * YROWB);
        #pragma unroll
        for (int i = 0; i < 36; i++)
            yrow[i] = __halves2half2(hl[2 * i], hl[2 * i + 1]);
        sqs[p] = sq * LOG2E2;
        auxT[0 * AUXT_STRIDE + p] = __float2half_rn(timg[p]);
        auxT[1 * AUXT_STRIDE + p] = __float2half_rn(timg[NPIX + p]);
        auxT[2 * AUXT_STRIDE + p] = __float2half_rn(timg[2 * NPIX + p]);
        auxT[3 * AUXT_STRIDE + p] = __float2half_rn(1.f);
    }
    __syncthreads();

    // ---- warp geometry: 16 warps = 8 n-subblocks x 2 m-halves ----
    const int wid = tid >> 5, lane = tid & 31;
    const int wn = wid >> 1;
    const int wm2 = wid & 1;
    const int grb = nb * 256 + wn * 32;
    const uint32_t ybase = smem_u32(Yb);
    const int n4 = (lane >> 2) & 3;               // V col (0..3), lanes 4-7 duplicate
    const __half* vtrow = auxT + n4 * AUXT_STRIDE;

    // ---- A fragments hoisted ----
    uint32_t a[2][4][4], a8[2][2];
    {
        int row = lane & 15;
        int cb  = (lane >> 4) << 4;
        #pragma unroll
        for (int nt = 0; nt < 2; nt++) {
            #pragma unroll
            for (int ks = 0; ks < 4; ks++)
                LDSM4(a[nt][ks], ybase + (uint32_t)(grb + nt * 16 + row) * YROWB + ks * 32 + cb);
            LDSM2(a8[nt], ybase + (uint32_t)(grb + nt * 16 + row) * YROWB + 128);
        }
    }

    // packed scaled row norms + diag row ids, hoisted
    ull  s2[2][2];
    int  gR[2][2];
    #pragma unroll
    for (int nt = 0; nt < 2; nt++)
        #pragma unroll
        for (int h = 0; h < 2; h++) {
            int gr = grb + nt * 16 + h * 8 + (lane >> 2);
            gR[nt][h] = gr;
            float s = sqs[gr];
            s2[nt][h] = pack2(s, s);
        }

    const ull neg2 = pack2(NEG2L2, NEG2L2);
    float O[2][4] = {{0.f,0.f,0.f,0.f},{0.f,0.f,0.f,0.f}};  // cols: S0,S1,S2,den

    // ---- stream m: 8 blocks of 128; warp's 64-col half in 2 groups of 32 ----
    for (int mb = 0; mb < 8; mb++) {
        #pragma unroll
        for (int g = 0; g < 2; g++) {
            const int mgb = mb * 128 + wm2 * 64 + g * 32;
            float c[2][4][4];
            #pragma unroll
            for (int nt = 0; nt < 2; nt++)
                #pragma unroll
                for (int mt = 0; mt < 4; mt++)
                    c[nt][mt][0] = c[nt][mt][1] = c[nt][mt][2] = c[nt][mt][3] = 0.f;

            #pragma unroll
            for (int ks = 0; ks < 4; ks++) {
                uint32_t b[8];
                #pragma unroll
                for (int bt = 0; bt < 2; bt++) {
                    int row = mgb + bt * 16 + (lane & 7) + ((lane >> 4) << 3);
                    int cb  = ks * 32 + (((lane >> 3) & 1) << 4);
                    LDSM4(&b[bt * 4], ybase + (uint32_t)row * YROWB + cb);
                }
                #pragma unroll
                for (int nt = 0; nt < 2; nt++)
                    #pragma unroll
                    for (int mt = 0; mt < 4; mt++) {
                        int bi = (mt >> 1) * 4 + (mt & 1) * 2;
                        MMA16816(c[nt][mt], a[nt][ks], b[bi], b[bi + 1]);
                    }
            }
            {   // k8 tail (cols 64..71)
                uint32_t b8[4];
                int row = mgb + (lane >> 3) * 8 + (lane & 7);
                LDSM4(b8, ybase + (uint32_t)row * YROWB + 128);
                #pragma unroll
                for (int nt = 0; nt < 2; nt++)
                    #pragma unroll
                    for (int mt = 0; mt < 4; mt++)
                        MMA16808(c[nt][mt], a8[nt], b8[mt]);
            }

            // ---- epilogue: half-group interleave (weights mt-pair -> PV MMA) ----
            const bool dg = (mgb == grb);           // warp-uniform diag block
            #pragma unroll
            for (int half = 0; half < 2; half++) {
                // prefetch V rows for this half's PV step
                const int mk0 = mgb + half * 16 + ((lane & 3) << 1);
                uint32_t b0 = *(const uint32_t*)(vtrow + mk0);
                uint32_t b1 = *(const uint32_t*)(vtrow + mk0 + 8);

                uint32_t wreg[2][2][2];
                #pragma unroll
                for (int mi = 0; mi < 2; mi++) {
                    const int mt = half * 2 + mi;
                    const int c0 = mgb + mt * 8 + ((lane & 3) << 1);
                    const ull qm2 = *(const ull*)(sqs + c0);   // LDS.64 (pair of norms)
                    #pragma unroll
                    for (int nt = 0; nt < 2; nt++)
                        #pragma unroll
                        for (int h = 0; h < 2; h++) {
                            ull c2  = pack2(c[nt][mt][h * 2], c[nt][mt][h * 2 + 1]);
                            ull dd2 = fma2(c2, neg2, add2(s2[nt][h], qm2));
                            float2 dd = unpack2(dd2);
                            float t0 = sqrta(dd.x);
                            float t1 = sqrta(dd.y);
                            uint32_t w = ex2h2(cvt_h2(t1, t0) ^ 0x80008000u);
                            if (dg) {               // kill diag (incl. NaN halves)
                                if (gR[nt][h] == c0)     w &= 0xFFFF0000u;
                                if (gR[nt][h] == c0 + 1) w &= 0x0000FFFFu;
                            }
                            wreg[mi][nt][h] = w;
                        }
                }

                #pragma unroll
                for (int nt = 0; nt < 2; nt++) {
                    uint32_t pa[4] = { wreg[0][nt][0], wreg[0][nt][1],
                                       wreg[1][nt][0], wreg[1][nt][1] };
                    MMA16816(O[nt], pa, b0, b1);
                }
            }
        }
    }

    // ---- write per-half partials (timg dead; red overlay) ----
    const int j = lane & 3;
    #pragma unroll
    for (int nt = 0; nt < 2; nt++) {
        if (j < 2) {
            int rl = wn * 32 + nt * 16 + (lane >> 2);
            ((float2*)&red[wm2 * 256 + rl])[j]     = make_float2(O[nt][0], O[nt][1]);
            ((float2*)&red[wm2 * 256 + rl + 8])[j] = make_float2(O[nt][2], O[nt][3]);
        }
    }
    __syncthreads();

    if (tid < 256) {
        float4 p0 = red[tid], p1 = red[256 + tid];
        float inv = 1.f / (p0.w + p1.w);
        int n = nb * 256 + tid;
        int gp = gb + (n >> 5) * IMG + (n & 31);
        out[gp]                 = (p0.x + p1.x) * inv;
        out[IMG * IMG + gp]     = (p0.y + p1.y) * inv;
        out[2 * IMG * IMG + gp] = (p0.z + p1.z) * inv;
    }
}

extern "C" void kernel_launch(void* const* d_in, const int* in_sizes, int n_in,
                              void* d_out, int out_size)
{
    (void)in_sizes; (void)n_in; (void)out_size;
    const float* img = (const float*)d_in[0];
    float* out = (float*)d_out;
    cudaFuncSetAttribute(nlm_hmma_kernel, cudaFuncAttributeMaxDynamicSharedMemorySize, SMEM_TOTAL);
    nlm_hmma_kernel<<<400, 512, SMEM_TOTAL>>>(img, out);
}

// round 17
// speedup vs baseline: 1.1738x; 1.1738x over previous
#include <cuda_runtime.h>
#include <cuda_fp16.h>
#include <stdint.h>
#include <math.h>

#define IMG   320
#define NPIX  1024
#define YROWB 144           // 72 halfs; stride%128=16 -> conflict-free ldmatrix

// shared layout (bytes): red overlays timg (timg dead after build)
#define SM_TIMG 0           // 12288 B (red: float4[512]=8KB after main loop)
#define SM_SQS  12288       // float[1024]: sq * log2e^2
#define SM_AUXT 16384       // half[4][1032]: V^T rows {I0, I1, I2, 1}
#define AUXT_STRIDE 1032
#define SM_Y    24704       // half[1024][72] (base%128==0 keeps bank layout)
#define SMEM_TOTAL (SM_Y + NPIX * YROWB)   // 172160

#define LOG2E2  2.0813689810056077f     // (log2 e)^2
#define NEG2L2 (-4.1627379620112153f)   // -2*(log2 e)^2

typedef unsigned long long ull;

__device__ __forceinline__ uint32_t smem_u32(const void* p) {
    uint32_t a;
    asm("{ .reg .u64 t; cvta.to.shared.u64 t, %1; cvt.u32.u64 %0, t; }" : "=r"(a) : "l"(p));
    return a;
}
__device__ __forceinline__ ull fma2(ull a, ull b, ull c) {
    ull d; asm("fma.rn.f32x2 %0, %1, %2, %3;" : "=l"(d) : "l"(a), "l"(b), "l"(c));
    return d;
}
__device__ __forceinline__ ull add2(ull a, ull b) {
    ull d; asm("add.rn.f32x2 %0, %1, %2;" : "=l"(d) : "l"(a), "l"(b));
    return d;
}
__device__ __forceinline__ ull pack2(float lo, float hi) {
    ull d; asm("mov.b64 %0, {%1, %2};" : "=l"(d) : "f"(lo), "f"(hi));
    return d;
}
__device__ __forceinline__ float2 unpack2(ull v) {
    float lo, hi; asm("mov.b64 {%0, %1}, %2;" : "=f"(lo), "=f"(hi) : "l"(v));
    return make_float2(lo, hi);
}
__device__ __forceinline__ float sqrta(float x) {
    float y; asm("sqrt.approx.f32 %0, %1;" : "=f"(y) : "f"(x)); return y;
}
__device__ __forceinline__ uint32_t cvt_h2(float hi, float lo) {   // h1=hi, h0=lo
    uint32_t r; asm("cvt.rn.f16x2.f32 %0, %1, %2;" : "=r"(r) : "f"(hi), "f"(lo));
    return r;
}
__device__ __forceinline__ uint32_t ex2h2(uint32_t a) {            // MUFU, 2 results
    uint32_t r; asm("ex2.approx.f16x2 %0, %1;" : "=r"(r) : "r"(a));
    return r;
}

#define LDSM4(r, addr) \
    asm volatile("ldmatrix.sync.aligned.m8n8.x4.shared.b16 {%0,%1,%2,%3}, [%4];" \
        : "=r"((r)[0]), "=r"((r)[1]), "=r"((r)[2]), "=r"((r)[3]) : "r"(addr))
#define LDSM2(r, addr) \
    asm volatile("ldmatrix.sync.aligned.m8n8.x2.shared.b16 {%0,%1}, [%2];" \
        : "=r"((r)[0]), "=r"((r)[1]) : "r"(addr))
#define MMA16816(c, a, b0, b1) \
    asm volatile("mma.sync.aligned.m16n8k16.row.col.f32.f16.f16.f32 " \
        "{%0,%1,%2,%3}, {%4,%5,%6,%7}, {%8,%9}, {%0,%1,%2,%3};" \
        : "+f"((c)[0]), "+f"((c)[1]), "+f"((c)[2]), "+f"((c)[3]) \
        : "r"((a)[0]), "r"((a)[1]), "r"((a)[2]), "r"((a)[3]), "r"(b0), "r"(b1))
#define MMA16808(c, a, b0) \
    asm volatile("mma.sync.aligned.m16n8k8.row.col.f32.f16.f16.f32 " \
        "{%0,%1,%2,%3}, {%4,%5}, {%6}, {%0,%1,%2,%3};" \
        : "+f"((c)[0]), "+f"((c)[1]), "+f"((c)[2]), "+f"((c)[3]) \
        : "r"((a)[0]), "r"((a)[1]), "r"(b0))

__global__ __launch_bounds__(512, 1)
void nlm_hmma_kernel(const float* __restrict__ img, float* __restrict__ out)
{
    extern __shared__ char sm[];
    float*   timg = (float*)(sm + SM_TIMG);
    float4*  red  = (float4*)(sm + SM_TIMG);      // overlays timg after main loop
    float*   sqs  = (float*)(sm + SM_SQS);
    __half*  auxT = (__half*)(sm + SM_AUXT);
    char*    Yb   = sm + SM_Y;

    const int bid  = blockIdx.x;
    const int tile = bid >> 2, nb = bid & 3;      // 256 rows per CTA
    const int ti = tile / 10, tj = tile % 10;
    const int tid = threadIdx.x;
    const int gb = ti * 32 * IMG + tj * 32;

    // ---- tile image -> smem ----
    for (int i = tid; i < 3 * NPIX; i += 512) {
        int ch = i >> 10, pix = i & 1023;
        timg[i] = img[ch * (IMG * IMG) + gb + (pix >> 5) * IMG + (pix & 31)];
    }
    __syncthreads();

    // ---- build fp16 features Y[1024][72] + V^T (fp16) + scaled norms ----
    for (int p = tid; p < NPIX; p += 512) {
        int r = p >> 5, c = p & 31;
        __half hl[72];
        float sq = 0.f;
        #pragma unroll
        for (int k = 0; k < 25; k++) {
            if (k == 12) continue;
            int kk = (k < 12) ? k : k - 1;
            int rr = min(max(r + k / 5 - 2, 0), 31);
            int cc = min(max(c + k % 5 - 2, 0), 31);
            int off = rr * 32 + cc;
            #pragma unroll
            for (int ch = 0; ch < 3; ch++) {
                float x = timg[ch * NPIX + off];
                __half h = __float2half_rn(x);
                float xr = __half2float(h);
                sq = fmaf(xr, xr, sq);
                hl[ch * 24 + kk] = h;
            }
        }
        __half2* yrow = (__half2*)(Yb + p * YROWB);
        #pragma unroll
        for (int i = 0; i < 36; i++)
            yrow[i] = __halves2half2(hl[2 * i], hl[2 * i + 1]);
        sqs[p] = sq * LOG2E2;
        auxT[0 * AUXT_STRIDE + p] = __float2half_rn(timg[p]);
        auxT[1 * AUXT_STRIDE + p] = __float2half_rn(timg[NPIX + p]);
        auxT[2 * AUXT_STRIDE + p] = __float2half_rn(timg[2 * NPIX + p]);
        auxT[3 * AUXT_STRIDE + p] = __float2half_rn(1.f);
    }
    __syncthreads();

    // ---- warp geometry: 16 warps = 8 n-subblocks x 2 m-halves ----
    const int wid = tid >> 5, lane = tid & 31;
    const int wn = wid >> 1;
    const int wm2 = wid & 1;
    const int grb = nb * 256 + wn * 32;
    const uint32_t ybase = smem_u32(Yb);
    const int n4 = (lane >> 2) & 3;               // V col (0..3), lanes 4-7 duplicate
    const __half* vtrow = auxT + n4 * AUXT_STRIDE;

    // ---- A fragments hoisted ----
    uint32_t a[2][4][4], a8[2][2];
    {
        int row = lane & 15;
        int cb  = (lane >> 4) << 4;
        #pragma unroll
        for (int nt = 0; nt < 2; nt++) {
            #pragma unroll
            for (int ks = 0; ks < 4; ks++)
                LDSM4(a[nt][ks], ybase + (uint32_t)(grb + nt * 16 + row) * YROWB + ks * 32 + cb);
            LDSM2(a8[nt], ybase + (uint32_t)(grb + nt * 16 + row) * YROWB + 128);
        }
    }

    // packed scaled row norms + diag row ids, hoisted
    ull  s2[2][2];
    int  gR[2][2];
    #pragma unroll
    for (int nt = 0; nt < 2; nt++)
        #pragma unroll
        for (int h = 0; h < 2; h++) {
            int gr = grb + nt * 16 + h * 8 + (lane >> 2);
            gR[nt][h] = gr;
            float s = sqs[gr];
            s2[nt][h] = pack2(s, s);
        }

    const ull neg2 = pack2(NEG2L2, NEG2L2);
    float O[2][4] = {{0.f,0.f,0.f,0.f},{0.f,0.f,0.f,0.f}};  // cols: S0,S1,S2,den

    // ---- stream m: 8 blocks of 128; warp's 64-col half in 2 groups of 32 ----
    for (int mb = 0; mb < 8; mb++) {
        #pragma unroll
        for (int g = 0; g < 2; g++) {
            const int mgb = mb * 128 + wm2 * 64 + g * 32;
            float c[2][4][4];
            #pragma unroll
            for (int nt = 0; nt < 2; nt++)
                #pragma unroll
                for (int mt = 0; mt < 4; mt++)
                    c[nt][mt][0] = c[nt][mt][1] = c[nt][mt][2] = c[nt][mt][3] = 0.f;

            #pragma unroll
            for (int ks = 0; ks < 4; ks++) {
                uint32_t b[8];
                #pragma unroll
                for (int bt = 0; bt < 2; bt++) {
                    int row = mgb + bt * 16 + (lane & 7) + ((lane >> 4) << 3);
                    int cb  = ks * 32 + (((lane >> 3) & 1) << 4);
                    LDSM4(&b[bt * 4], ybase + (uint32_t)row * YROWB + cb);
                }
                #pragma unroll
                for (int nt = 0; nt < 2; nt++)
                    #pragma unroll
                    for (int mt = 0; mt < 4; mt++) {
                        int bi = (mt >> 1) * 4 + (mt & 1) * 2;
                        MMA16816(c[nt][mt], a[nt][ks], b[bi], b[bi + 1]);
                    }
            }
            {   // k8 tail (cols 64..71)
                uint32_t b8[4];
                int row = mgb + (lane >> 3) * 8 + (lane & 7);
                LDSM4(b8, ybase + (uint32_t)row * YROWB + 128);
                #pragma unroll
                for (int nt = 0; nt < 2; nt++)
                    #pragma unroll
                    for (int mt = 0; mt < 4; mt++)
                        MMA16808(c[nt][mt], a8[nt], b8[mt]);
            }

            // ---- weights into fp16 P fragments ----
            const bool dg = (mgb == grb);           // warp-uniform diag block
            uint32_t wreg[4][2][2];
            #pragma unroll
            for (int mt = 0; mt < 4; mt++) {
                const int c0 = mgb + mt * 8 + ((lane & 3) << 1);
                const ull qm2 = *(const ull*)(sqs + c0);   // LDS.64 (pair of norms)
                #pragma unroll
                for (int nt = 0; nt < 2; nt++)
                    #pragma unroll
                    for (int h = 0; h < 2; h++) {
                        ull c2  = pack2(c[nt][mt][h * 2], c[nt][mt][h * 2 + 1]);
                        ull dd2 = fma2(c2, neg2, add2(s2[nt][h], qm2));
                        float2 dd = unpack2(dd2);
                        float t0 = sqrta(dd.x);
                        float t1 = sqrta(dd.y);
                        uint32_t w = ex2h2(cvt_h2(t1, t0) ^ 0x80008000u);
                        if (dg) {                   // kill diag (incl. NaN halves)
                            if (gR[nt][h] == c0)     w &= 0xFFFF0000u;
                            if (gR[nt][h] == c0 + 1) w &= 0x0000FFFFu;
                        }
                        wreg[mt][nt][h] = w;
                    }
            }

            // ---- P @ V : 2 k16 steps x 2 nt, V = [I0,I1,I2,1] fp16 ----
            #pragma unroll
            for (int ks2 = 0; ks2 < 2; ks2++) {
                const int mk0 = mgb + ks2 * 16 + ((lane & 3) << 1);
                uint32_t b0 = *(const uint32_t*)(vtrow + mk0);
                uint32_t b1 = *(const uint32_t*)(vtrow + mk0 + 8);
                #pragma unroll
                for (int nt = 0; nt < 2; nt++) {
                    uint32_t pa[4] = { wreg[ks2 * 2][nt][0],     wreg[ks2 * 2][nt][1],
                                       wreg[ks2 * 2 + 1][nt][0], wreg[ks2 * 2 + 1][nt][1] };
                    MMA16816(O[nt], pa, b0, b1);
                }
            }
        }
    }

    // ---- write per-half partials (timg dead; red overlay) ----
    const int j = lane & 3;
    #pragma unroll
    for (int nt = 0; nt < 2; nt++) {
        if (j < 2) {
            int rl = wn * 32 + nt * 16 + (lane >> 2);
            ((float2*)&red[wm2 * 256 + rl])[j]     = make_float2(O[nt][0], O[nt][1]);
            ((float2*)&red[wm2 * 256 + rl + 8])[j] = make_float2(O[nt][2], O[nt][3]);
        }
    }
    __syncthreads();

    if (tid < 256) {
        float4 p0 = red[tid], p1 = red[256 + tid];
        float inv = 1.f / (p0.w + p1.w);
        int n = nb * 256 + tid;
        int gp = gb + (n >> 5) * IMG + (n & 31);
        out[gp]                 = (p0.x + p1.x) * inv;
        out[IMG * IMG + gp]     = (p0.y + p1.y) * inv;
        out[2 * IMG * IMG + gp] = (p0.z + p1.z) * inv;
    }
}

extern "C" void kernel_launch(void* const* d_in, const int* in_sizes, int n_in,
                              void* d_out, int out_size)
{
    (void)in_sizes; (void)n_in; (void)out_size;
    const float* img = (const float*)d_in[0];
    float* out = (float*)d_out;
    cudaFuncSetAttribute(nlm_hmma_kernel, cudaFuncAttributeMaxDynamicSharedMemorySize, SMEM_TOTAL);
    nlm_hmma_kernel<<<400, 512, SMEM_TOTAL>>>(img, out);
}